// round 7
// baseline (speedup 1.0000x reference)
#include <cuda_runtime.h>
#include <math.h>

// ---------------- problem constants ----------------
constexpr int B   = 32;
constexpr int D   = 256;
constexpr int H   = 64;
constexpr int W   = 64;
constexpr int HW  = H * W;      // 4096
constexpr int K   = 256;
constexpr int DFF = 2048;

#define TEMP_INV  14.2857142857142857f   // 1/0.07
#define EPS_F     1e-6f
#define NORM_EPS  1e-12f
#define LN_EPS    1e-5f

// ---------------- device scratch (static, allocation-free) ----------------
__device__ float g_tn[B * K * D];                 // normalized tgt        (8.4 MB)
__device__ float g_invnx[B * HW];                 // 1/||x(:,hw)||         (0.5 MB)
__device__ float g_xsum[B * D];                   // sum_hw x[d][hw]
__device__ float g_p[B * K * HW];                 // dots -> softmax probs (134 MB)
__device__ float g_S[B * K];                      // sum_hw p
__device__ float g_t[B * K * D];                  // after LN1             (8.4 MB)
__device__ float g_h[B * K * DFF];                // relu hidden           (67 MB)
__device__ float g_y[B * K * D];                  // pre-LN buffer         (8.4 MB)

// ---------------- helpers ----------------
__device__ __forceinline__ float block_reduce_sum_256(float v, float* sm) {
    #pragma unroll
    for (int o = 16; o > 0; o >>= 1) v += __shfl_down_sync(0xffffffffu, v, o);
    int lane = threadIdx.x & 31, wid = threadIdx.x >> 5;
    if (lane == 0) sm[wid] = v;
    __syncthreads();
    if (wid == 0) {
        float w = (lane < 8) ? sm[lane] : 0.0f;
        #pragma unroll
        for (int o = 4; o > 0; o >>= 1) w += __shfl_down_sync(0xffffffffu, w, o);
        if (lane == 0) sm[0] = w;
    }
    __syncthreads();
    float r = sm[0];
    __syncthreads();
    return r;
}

// ---------------- small prep kernels ----------------

// L2-normalize tgt rows: one block per (b,k) row of 256
__global__ void k_tn(const float* __restrict__ tgt) {
    __shared__ float sm[8];
    int row = blockIdx.x;                       // b*K + k
    float v = tgt[row * D + threadIdx.x];
    float ss = block_reduce_sum_256(v * v, sm);
    float inv = 1.0f / fmaxf(sqrtf(ss), NORM_EPS);
    g_tn[row * D + threadIdx.x] = v * inv;
}

// per-(b,hw) inverse column norm of x
__global__ void k_invnx(const float* __restrict__ x) {
    int idx = blockIdx.x * 256 + threadIdx.x;   // b*HW + hw
    int b = idx >> 12, hw = idx & (HW - 1);
    const float* xp = x + (size_t)b * D * HW + hw;
    float ss = 0.0f;
    #pragma unroll 8
    for (int d = 0; d < D; d++) { float v = xp[(size_t)d * HW]; ss += v * v; }
    g_invnx[idx] = 1.0f / fmaxf(sqrtf(ss), NORM_EPS);
}

// per-(b,d) spatial sum of x
__global__ void k_xsum(const float* __restrict__ x) {
    __shared__ float sm[8];
    int bd = blockIdx.x;                        // b*D + d
    const float* xp = x + (size_t)bd * HW;
    float s = 0.0f;
    for (int i = threadIdx.x; i < HW; i += 256) s += xp[i];
    s = block_reduce_sum_256(s, sm);
    if (threadIdx.x == 0) g_xsum[bd] = s;
}

// ---------------- dots GEMM (NN): dots[k][hw] = invnx[hw] * sum_d tn[k][d]*x[d][hw] ----------------
// register-prefetch pipeline: next chunk's global loads issued before the compute block
__global__ void __launch_bounds__(256) k_dots(const float* __restrict__ x) {
    __shared__ float As[16][136];   // As[dd][k]  (tn, transposed on load)
    __shared__ float Bs[16][136];   // Bs[dd][hw] (x rows, natural)
    int b   = blockIdx.z;
    int hw0 = blockIdx.x * 128;
    int k0  = blockIdx.y * 128;
    int tid = threadIdx.x;
    int tx = tid & 15, ty = tid >> 4;

    float acc[8][8];
    #pragma unroll
    for (int r = 0; r < 8; r++)
        #pragma unroll
        for (int c = 0; c < 8; c++) acc[r][c] = 0.0f;

    const float* Ab = g_tn + (b * K + k0) * D;
    const float* Bb = x + (size_t)b * D * HW + hw0;

    float4 ra[2], rb[2];
    // prefetch chunk 0
    #pragma unroll
    for (int i = 0; i < 2; i++) {
        int f4 = tid + i * 256;
        int arow = f4 >> 2, ac4 = (f4 & 3) * 4;
        ra[i] = *(const float4*)(Ab + arow * D + ac4);
        int brow = f4 >> 5, bc4 = (f4 & 31) * 4;
        rb[i] = *(const float4*)(Bb + (size_t)brow * HW + bc4);
    }

    for (int dc = 0; dc < D; dc += 16) {
        // stage prefetched chunk to smem
        #pragma unroll
        for (int i = 0; i < 2; i++) {
            int f4 = tid + i * 256;
            int arow = f4 >> 2, ac4 = (f4 & 3) * 4;
            As[ac4 + 0][arow] = ra[i].x; As[ac4 + 1][arow] = ra[i].y;
            As[ac4 + 2][arow] = ra[i].z; As[ac4 + 3][arow] = ra[i].w;
            int brow = f4 >> 5, bc4 = (f4 & 31) * 4;
            Bs[brow][bc4 + 0] = rb[i].x; Bs[brow][bc4 + 1] = rb[i].y;
            Bs[brow][bc4 + 2] = rb[i].z; Bs[brow][bc4 + 3] = rb[i].w;
        }
        __syncthreads();
        // prefetch next chunk (overlaps with compute below)
        if (dc + 16 < D) {
            #pragma unroll
            for (int i = 0; i < 2; i++) {
                int f4 = tid + i * 256;
                int arow = f4 >> 2, ac4 = (f4 & 3) * 4;
                ra[i] = *(const float4*)(Ab + arow * D + dc + 16 + ac4);
                int brow = f4 >> 5, bc4 = (f4 & 31) * 4;
                rb[i] = *(const float4*)(Bb + (size_t)(dc + 16 + brow) * HW + bc4);
            }
        }
        #pragma unroll
        for (int t = 0; t < 16; t++) {
            float a[8], bb[8];
            *(float4*)(a)      = *(float4*)&As[t][ty * 8];
            *(float4*)(a + 4)  = *(float4*)&As[t][ty * 8 + 4];
            *(float4*)(bb)     = *(float4*)&Bs[t][tx * 8];
            *(float4*)(bb + 4) = *(float4*)&Bs[t][tx * 8 + 4];
            #pragma unroll
            for (int r = 0; r < 8; r++)
                #pragma unroll
                for (int c = 0; c < 8; c++) acc[r][c] += a[r] * bb[c];
        }
        __syncthreads();
    }

    float inx[8];
    *(float4*)(inx)     = *(const float4*)(g_invnx + b * HW + hw0 + tx * 8);
    *(float4*)(inx + 4) = *(const float4*)(g_invnx + b * HW + hw0 + tx * 8 + 4);
    #pragma unroll
    for (int r = 0; r < 8; r++) {
        int k = k0 + ty * 8 + r;
        float* out = g_p + (size_t)(b * K + k) * HW + hw0 + tx * 8;
        float4 v0 = make_float4(acc[r][0] * inx[0], acc[r][1] * inx[1],
                                acc[r][2] * inx[2], acc[r][3] * inx[3]);
        float4 v1 = make_float4(acc[r][4] * inx[4], acc[r][5] * inx[5],
                                acc[r][6] * inx[6], acc[r][7] * inx[7]);
        *(float4*)(out)     = v0;
        *(float4*)(out + 4) = v1;
    }
}

// ---------------- softmax over K per (b,hw) ----------------
// dots are cosine/0.07 in [-14.3, 14.3] -> exp bounded by 1.6e6, no max-shift needed
__global__ void k_softmax() {
    int idx = blockIdx.x * 256 + threadIdx.x;   // b*HW + hw
    int b = idx >> 12, hw = idx & (HW - 1);
    float* p = g_p + (size_t)b * K * HW + hw;
    float s = 0.0f;
    for (int k = 0; k < K; k++) {
        float e = __expf(p[(size_t)k * HW] * TEMP_INV);
        s += e;
        p[(size_t)k * HW] = e;
    }
    float rs = 1.0f / s;
    for (int k = 0; k < K; k++) p[(size_t)k * HW] *= rs;
}

// deterministic spatial sum of p per (b,k)
__global__ void k_S() {
    __shared__ float sm[8];
    int bk = blockIdx.x;
    const float* p = g_p + (size_t)bk * HW;
    float s = 0.0f;
    for (int i = threadIdx.x; i < HW; i += 256) s += p[i];
    s = block_reduce_sum_256(s, sm);
    if (threadIdx.x == 0) g_S[bk] = s;
}

// ---------------- shared TN-GEMM tile: C[i][j] = sum_t A[i*lda+t]*B[j*ldb+t] ----------------
// both operands K-major; register-prefetch pipeline
__device__ __forceinline__ void gemm_tn_tile(
    const float* __restrict__ A, int lda,
    const float* __restrict__ Bp, int ldb, int Kin,
    float (&acc)[8][8], float (*As)[136], float (*Bs)[136])
{
    int tid = threadIdx.x;
    int tx = tid & 15, ty = tid >> 4;

    float4 ra[2], rb[2];
    #pragma unroll
    for (int i = 0; i < 2; i++) {
        int f4 = tid + i * 256;
        int row = f4 >> 2, c4 = (f4 & 3) * 4;
        ra[i] = *(const float4*)(A  + (size_t)row * lda + c4);
        rb[i] = *(const float4*)(Bp + (size_t)row * ldb + c4);
    }

    for (int kc = 0; kc < Kin; kc += 16) {
        #pragma unroll
        for (int i = 0; i < 2; i++) {
            int f4 = tid + i * 256;
            int row = f4 >> 2, c4 = (f4 & 3) * 4;
            As[c4 + 0][row] = ra[i].x; As[c4 + 1][row] = ra[i].y;
            As[c4 + 2][row] = ra[i].z; As[c4 + 3][row] = ra[i].w;
            Bs[c4 + 0][row] = rb[i].x; Bs[c4 + 1][row] = rb[i].y;
            Bs[c4 + 2][row] = rb[i].z; Bs[c4 + 3][row] = rb[i].w;
        }
        __syncthreads();
        if (kc + 16 < Kin) {
            #pragma unroll
            for (int i = 0; i < 2; i++) {
                int f4 = tid + i * 256;
                int row = f4 >> 2, c4 = (f4 & 3) * 4;
                ra[i] = *(const float4*)(A  + (size_t)row * lda + kc + 16 + c4);
                rb[i] = *(const float4*)(Bp + (size_t)row * ldb + kc + 16 + c4);
            }
        }
        #pragma unroll
        for (int t = 0; t < 16; t++) {
            float a[8], bb[8];
            *(float4*)(a)      = *(float4*)&As[t][ty * 8];
            *(float4*)(a + 4)  = *(float4*)&As[t][ty * 8 + 4];
            *(float4*)(bb)     = *(float4*)&Bs[t][tx * 8];
            *(float4*)(bb + 4) = *(float4*)&Bs[t][tx * 8 + 4];
            #pragma unroll
            for (int r = 0; r < 8; r++)
                #pragma unroll
                for (int c = 0; c < 8; c++) acc[r][c] += a[r] * bb[c];
        }
        __syncthreads();
    }
}

// ---------------- tgt2: y = tgt + (P x^T + EPS*xsum)/S_tot ----------------
__global__ void __launch_bounds__(256) k_tgt2(const float* __restrict__ x,
                                              const float* __restrict__ tgt) {
    __shared__ float As[16][136], Bs[16][136];
    int b  = blockIdx.z;
    int k0 = blockIdx.y * 128;
    int d0 = blockIdx.x * 128;
    float acc[8][8];
    #pragma unroll
    for (int r = 0; r < 8; r++)
        #pragma unroll
        for (int c = 0; c < 8; c++) acc[r][c] = 0.0f;

    gemm_tn_tile(g_p + (size_t)(b * K + k0) * HW, HW,
                 x + (size_t)(b * D + d0) * HW, HW, HW, acc, As, Bs);

    int tx = threadIdx.x & 15, ty = threadIdx.x >> 4;
    float rS[8], xs[8];
    #pragma unroll
    for (int r = 0; r < 8; r++)
        rS[r] = 1.0f / (g_S[b * K + k0 + ty * 8 + r] + EPS_F * (float)HW);
    #pragma unroll
    for (int c = 0; c < 8; c++)
        xs[c] = g_xsum[b * D + d0 + tx * 8 + c] * EPS_F;

    #pragma unroll
    for (int r = 0; r < 8; r++) {
        int base = (b * K + k0 + ty * 8 + r) * D + d0 + tx * 8;
        float4 t0 = *(const float4*)(tgt + base);
        float4 t1 = *(const float4*)(tgt + base + 4);
        float4 v0 = make_float4((acc[r][0] + xs[0]) * rS[r] + t0.x,
                                (acc[r][1] + xs[1]) * rS[r] + t0.y,
                                (acc[r][2] + xs[2]) * rS[r] + t0.z,
                                (acc[r][3] + xs[3]) * rS[r] + t0.w);
        float4 v1 = make_float4((acc[r][4] + xs[4]) * rS[r] + t1.x,
                                (acc[r][5] + xs[5]) * rS[r] + t1.y,
                                (acc[r][6] + xs[6]) * rS[r] + t1.z,
                                (acc[r][7] + xs[7]) * rS[r] + t1.w);
        *(float4*)(g_y + base)     = v0;
        *(float4*)(g_y + base + 4) = v1;
    }
}

// ---------------- LayerNorm 1: g_t = LN(g_y) * gamma + beta ----------------
// (device globals referenced INSIDE the kernel; only real inputs passed as args)
__global__ void k_ln1(const float* __restrict__ gamma,
                      const float* __restrict__ beta) {
    __shared__ float sm[8];
    int row = blockIdx.x;
    float v  = g_y[row * D + threadIdx.x];
    float mu = block_reduce_sum_256(v, sm) * (1.0f / D);
    float d  = v - mu;
    float var = block_reduce_sum_256(d * d, sm) * (1.0f / D);
    float r = rsqrtf(var + LN_EPS);
    g_t[row * D + threadIdx.x] = d * r * gamma[threadIdx.x] + beta[threadIdx.x];
}

// ---------------- LayerNorm 2: out = LN(g_y) * gamma + beta ----------------
__global__ void k_ln2(const float* __restrict__ gamma,
                      const float* __restrict__ beta,
                      float* __restrict__ dst) {
    __shared__ float sm[8];
    int row = blockIdx.x;
    float v  = g_y[row * D + threadIdx.x];
    float mu = block_reduce_sum_256(v, sm) * (1.0f / D);
    float d  = v - mu;
    float var = block_reduce_sum_256(d * d, sm) * (1.0f / D);
    float r = rsqrtf(var + LN_EPS);
    dst[row * D + threadIdx.x] = d * r * gamma[threadIdx.x] + beta[threadIdx.x];
}

// ---------------- FFN1: h = relu(t @ w1^T + b1) ----------------
__global__ void __launch_bounds__(256) k_ffn1(const float* __restrict__ w1,
                                              const float* __restrict__ b1) {
    __shared__ float As[16][136], Bs[16][136];
    int m0 = blockIdx.y * 128;
    int f0 = blockIdx.x * 128;
    float acc[8][8];
    #pragma unroll
    for (int r = 0; r < 8; r++)
        #pragma unroll
        for (int c = 0; c < 8; c++) acc[r][c] = 0.0f;

    gemm_tn_tile(g_t + (size_t)m0 * D, D, w1 + (size_t)f0 * D, D, D, acc, As, Bs);

    int tx = threadIdx.x & 15, ty = threadIdx.x >> 4;
    float bias[8];
    *(float4*)(bias)     = *(const float4*)(b1 + f0 + tx * 8);
    *(float4*)(bias + 4) = *(const float4*)(b1 + f0 + tx * 8 + 4);
    #pragma unroll
    for (int r = 0; r < 8; r++) {
        int base = (m0 + ty * 8 + r) * DFF + f0 + tx * 8;
        float4 v0 = make_float4(fmaxf(acc[r][0] + bias[0], 0.0f),
                                fmaxf(acc[r][1] + bias[1], 0.0f),
                                fmaxf(acc[r][2] + bias[2], 0.0f),
                                fmaxf(acc[r][3] + bias[3], 0.0f));
        float4 v1 = make_float4(fmaxf(acc[r][4] + bias[4], 0.0f),
                                fmaxf(acc[r][5] + bias[5], 0.0f),
                                fmaxf(acc[r][6] + bias[6], 0.0f),
                                fmaxf(acc[r][7] + bias[7], 0.0f));
        *(float4*)(g_h + base)     = v0;
        *(float4*)(g_h + base + 4) = v1;
    }
}

// ---------------- FFN2 + residual: y = t + h @ w2^T + b2 ----------------
__global__ void __launch_bounds__(256) k_ffn2(const float* __restrict__ w2,
                                              const float* __restrict__ b2) {
    __shared__ float As[16][136], Bs[16][136];
    int m0 = blockIdx.y * 128;
    int d0 = blockIdx.x * 128;
    float acc[8][8];
    #pragma unroll
    for (int r = 0; r < 8; r++)
        #pragma unroll
        for (int c = 0; c < 8; c++) acc[r][c] = 0.0f;

    gemm_tn_tile(g_h + (size_t)m0 * DFF, DFF, w2 + (size_t)d0 * DFF, DFF, DFF, acc, As, Bs);

    int tx = threadIdx.x & 15, ty = threadIdx.x >> 4;
    float bias[8];
    *(float4*)(bias)     = *(const float4*)(b2 + d0 + tx * 8);
    *(float4*)(bias + 4) = *(const float4*)(b2 + d0 + tx * 8 + 4);
    #pragma unroll
    for (int r = 0; r < 8; r++) {
        int base = (m0 + ty * 8 + r) * D + d0 + tx * 8;
        float4 t0 = *(const float4*)(g_t + base);
        float4 t1 = *(const float4*)(g_t + base + 4);
        float4 v0 = make_float4(acc[r][0] + bias[0] + t0.x,
                                acc[r][1] + bias[1] + t0.y,
                                acc[r][2] + bias[2] + t0.z,
                                acc[r][3] + bias[3] + t0.w);
        float4 v1 = make_float4(acc[r][4] + bias[4] + t1.x,
                                acc[r][5] + bias[5] + t1.y,
                                acc[r][6] + bias[6] + t1.z,
                                acc[r][7] + bias[7] + t1.w);
        *(float4*)(g_y + base)     = v0;
        *(float4*)(g_y + base + 4) = v1;
    }
}

// ---------------- launch ----------------
extern "C" void kernel_launch(void* const* d_in, const int* in_sizes, int n_in,
                              void* d_out, int out_size) {
    const float* x   = (const float*)d_in[0];
    const float* tgt = (const float*)d_in[1];
    const float* w1  = (const float*)d_in[2];
    const float* b1  = (const float*)d_in[3];
    const float* w2  = (const float*)d_in[4];
    const float* b2  = (const float*)d_in[5];
    const float* g2  = (const float*)d_in[6];
    const float* be2 = (const float*)d_in[7];
    const float* g3  = (const float*)d_in[8];
    const float* be3 = (const float*)d_in[9];
    float* out = (float*)d_out;

    k_tn   <<<B * K, 256>>>(tgt);
    k_invnx<<<(B * HW) / 256, 256>>>(x);
    k_xsum <<<B * D, 256>>>(x);

    k_dots <<<dim3(HW / 128, K / 128, B), 256>>>(x);
    k_softmax<<<(B * HW) / 256, 256>>>();
    k_S    <<<B * K, 256>>>();

    k_tgt2 <<<dim3(D / 128, K / 128, B), 256>>>(x, tgt);
    k_ln1  <<<B * K, 256>>>(g2, be2);

    k_ffn1 <<<dim3(DFF / 128, (B * K) / 128), 256>>>(w1, b1);
    k_ffn2 <<<dim3(D / 128, (B * K) / 128), 256>>>(w2, b2);
    k_ln2  <<<B * K, 256>>>(g3, be3, out);
}

// round 8
// speedup vs baseline: 1.4890x; 1.4890x over previous
#include <cuda_runtime.h>
#include <math.h>

// ---------------- problem constants ----------------
constexpr int B   = 32;
constexpr int D   = 256;
constexpr int H   = 64;
constexpr int W   = 64;
constexpr int HW  = H * W;      // 4096
constexpr int K   = 256;
constexpr int DFF = 2048;

#define TEMP_INV  14.2857142857142857f   // 1/0.07
#define EPS_F     1e-6f
#define NORM_EPS  1e-12f
#define LN_EPS    1e-5f

// ---------------- device scratch (static, allocation-free) ----------------
__device__ float g_tn[B * K * D];
__device__ float g_invnx[B * HW];
__device__ float g_xsum[B * D];
__device__ float g_p[B * K * HW];
__device__ float g_S[B * K];
__device__ float g_t[B * K * D];
__device__ float g_h[B * K * DFF];
__device__ float g_y[B * K * D];

// ---------------- tf32 mma helpers ----------------
__device__ __forceinline__ void split_tf32(float v, unsigned &hi, unsigned &lo) {
    asm("cvt.rna.tf32.f32 %0, %1;" : "=r"(hi) : "f"(v));
    float r = v - __uint_as_float(hi);
    asm("cvt.rna.tf32.f32 %0, %1;" : "=r"(lo) : "f"(r));
}

__device__ __forceinline__ void mma_tf32(float (&c)[4], const unsigned (&a)[4],
                                         unsigned b0, unsigned b1) {
    asm("mma.sync.aligned.m16n8k8.row.col.f32.tf32.tf32.f32 "
        "{%0,%1,%2,%3}, {%4,%5,%6,%7}, {%8,%9}, {%0,%1,%2,%3};"
        : "+f"(c[0]), "+f"(c[1]), "+f"(c[2]), "+f"(c[3])
        : "r"(a[0]), "r"(a[1]), "r"(a[2]), "r"(a[3]), "r"(b0), "r"(b1));
}

__device__ __forceinline__ void cp_async16(void* smem_dst, const void* gsrc) {
    unsigned s = (unsigned)__cvta_generic_to_shared(smem_dst);
    asm volatile("cp.async.cg.shared.global [%0], [%1], 16;" :: "r"(s), "l"(gsrc));
}
#define CP_COMMIT()  asm volatile("cp.async.commit_group;")
#define CP_WAIT_1()  asm volatile("cp.async.wait_group 1;")
#define CP_WAIT_0()  asm volatile("cp.async.wait_group 0;")

// ---------------- staging: 128 rows x 16 floats, padded row stride 20 ----------------
__device__ __forceinline__ void stage_rows20(const float* __restrict__ src, int ld,
                                             int kc, float* dst, int tid) {
    #pragma unroll
    for (int i = 0; i < 2; i++) {
        int f = tid + i * 256;
        int row = f >> 2, q = (f & 3) * 4;
        cp_async16(dst + row * 20 + q, src + (size_t)row * ld + kc + q);
    }
}

// dots-B staging: 16 k-rows x 128 cols, row stride 136
__device__ __forceinline__ void stage_bdots(const float* __restrict__ src,
                                            int kc, float* dst, int tid) {
    #pragma unroll
    for (int i = 0; i < 2; i++) {
        int f = tid + i * 256;
        int kr = f >> 5, q = (f & 31) * 4;
        cp_async16(dst + kr * 136 + q, src + (size_t)(kc + kr) * HW + q);
    }
}

// ---------------- mma compute: TN form (A[m][k] rows-20, B[n][k] rows-20) ----------------
__device__ __forceinline__ void mma_compute_tn(const float* sA, const float* sB,
                                               float (&acc)[4][4][4],
                                               int lane, int wm, int wn) {
    int g = lane >> 2, t = lane & 3;
    #pragma unroll
    for (int kk = 0; kk < 16; kk += 8) {
        unsigned ah[4][4], al[4][4];
        #pragma unroll
        for (int i = 0; i < 4; i++) {
            int m = wm * 64 + i * 16;
            float v0 = sA[(m + g) * 20 + kk + t];
            float v1 = sA[(m + 8 + g) * 20 + kk + t];
            float v2 = sA[(m + g) * 20 + kk + 4 + t];
            float v3 = sA[(m + 8 + g) * 20 + kk + 4 + t];
            split_tf32(v0, ah[i][0], al[i][0]);
            split_tf32(v1, ah[i][1], al[i][1]);
            split_tf32(v2, ah[i][2], al[i][2]);
            split_tf32(v3, ah[i][3], al[i][3]);
        }
        #pragma unroll
        for (int j = 0; j < 4; j++) {
            int n = wn * 32 + j * 8;
            float u0 = sB[(n + g) * 20 + kk + t];
            float u1 = sB[(n + g) * 20 + kk + 4 + t];
            unsigned bh0, bl0, bh1, bl1;
            split_tf32(u0, bh0, bl0);
            split_tf32(u1, bh1, bl1);
            #pragma unroll
            for (int i = 0; i < 4; i++) {
                mma_tf32(acc[i][j], ah[i], bh0, bh1);
                mma_tf32(acc[i][j], ah[i], bl0, bl1);
                mma_tf32(acc[i][j], al[i], bh0, bh1);
            }
        }
    }
}

// dots variant: B in [k][n] layout (row stride 136)
__device__ __forceinline__ void mma_compute_dots(const float* sA, const float* sB,
                                                 float (&acc)[4][4][4],
                                                 int lane, int wm, int wn) {
    int g = lane >> 2, t = lane & 3;
    #pragma unroll
    for (int kk = 0; kk < 16; kk += 8) {
        unsigned ah[4][4], al[4][4];
        #pragma unroll
        for (int i = 0; i < 4; i++) {
            int m = wm * 64 + i * 16;
            float v0 = sA[(m + g) * 20 + kk + t];
            float v1 = sA[(m + 8 + g) * 20 + kk + t];
            float v2 = sA[(m + g) * 20 + kk + 4 + t];
            float v3 = sA[(m + 8 + g) * 20 + kk + 4 + t];
            split_tf32(v0, ah[i][0], al[i][0]);
            split_tf32(v1, ah[i][1], al[i][1]);
            split_tf32(v2, ah[i][2], al[i][2]);
            split_tf32(v3, ah[i][3], al[i][3]);
        }
        #pragma unroll
        for (int j = 0; j < 4; j++) {
            int n = wn * 32 + j * 8;
            float u0 = sB[(kk + t) * 136 + n + g];
            float u1 = sB[(kk + 4 + t) * 136 + n + g];
            unsigned bh0, bl0, bh1, bl1;
            split_tf32(u0, bh0, bl0);
            split_tf32(u1, bh1, bl1);
            #pragma unroll
            for (int i = 0; i < 4; i++) {
                mma_tf32(acc[i][j], ah[i], bh0, bh1);
                mma_tf32(acc[i][j], ah[i], bl0, bl1);
                mma_tf32(acc[i][j], al[i], bh0, bh1);
            }
        }
    }
}

// ---------------- TN GEMM driver with cp.async double buffering ----------------
__device__ inline void run_gemm_tn(const float* A, int lda, const float* Bp, int ldb,
                                   int Kin, float (&acc)[4][4][4],
                                   float* sA, float* sB) {
    int tid = threadIdx.x;
    int lane = tid & 31, w = tid >> 5, wm = w >> 2, wn = w & 3;
    stage_rows20(A, lda, 0, sA, tid);
    stage_rows20(Bp, ldb, 0, sB, tid);
    CP_COMMIT();
    int NC = Kin / 16;
    for (int c = 0; c < NC; c++) {
        float* cA = sA + (c & 1) * (128 * 20);
        float* cB = sB + (c & 1) * (128 * 20);
        if (c + 1 < NC) {
            stage_rows20(A, lda, (c + 1) * 16, sA + ((c + 1) & 1) * (128 * 20), tid);
            stage_rows20(Bp, ldb, (c + 1) * 16, sB + ((c + 1) & 1) * (128 * 20), tid);
            CP_COMMIT();
            CP_WAIT_1();
        } else {
            CP_WAIT_0();
        }
        __syncthreads();
        mma_compute_tn(cA, cB, acc, lane, wm, wn);
        __syncthreads();
    }
}

// ---------------- helpers ----------------
__device__ __forceinline__ float block_reduce_sum_256(float v, float* sm) {
    #pragma unroll
    for (int o = 16; o > 0; o >>= 1) v += __shfl_down_sync(0xffffffffu, v, o);
    int lane = threadIdx.x & 31, wid = threadIdx.x >> 5;
    if (lane == 0) sm[wid] = v;
    __syncthreads();
    if (wid == 0) {
        float w = (lane < 8) ? sm[lane] : 0.0f;
        #pragma unroll
        for (int o = 4; o > 0; o >>= 1) w += __shfl_down_sync(0xffffffffu, w, o);
        if (lane == 0) sm[0] = w;
    }
    __syncthreads();
    float r = sm[0];
    __syncthreads();
    return r;
}

// ---------------- small prep kernels ----------------
__global__ void k_tn(const float* __restrict__ tgt) {
    __shared__ float sm[8];
    int row = blockIdx.x;
    float v = tgt[row * D + threadIdx.x];
    float ss = block_reduce_sum_256(v * v, sm);
    float inv = 1.0f / fmaxf(sqrtf(ss), NORM_EPS);
    g_tn[row * D + threadIdx.x] = v * inv;
}

__global__ void k_invnx(const float* __restrict__ x) {
    int idx = blockIdx.x * 256 + threadIdx.x;
    int b = idx >> 12, hw = idx & (HW - 1);
    const float* xp = x + (size_t)b * D * HW + hw;
    float ss = 0.0f;
    #pragma unroll 8
    for (int d = 0; d < D; d++) { float v = xp[(size_t)d * HW]; ss += v * v; }
    g_invnx[idx] = 1.0f / fmaxf(sqrtf(ss), NORM_EPS);
}

__global__ void k_xsum(const float* __restrict__ x) {
    __shared__ float sm[8];
    int bd = blockIdx.x;
    const float* xp = x + (size_t)bd * HW;
    float s = 0.0f;
    for (int i = threadIdx.x; i < HW; i += 256) s += xp[i];
    s = block_reduce_sum_256(s, sm);
    if (threadIdx.x == 0) g_xsum[bd] = s;
}

// ---------------- dots: g_p[k][hw] = invnx[hw] * sum_d tn[k][d]*x[d][hw] ----------------
__global__ void __launch_bounds__(256) k_dots(const float* __restrict__ x) {
    __shared__ float sA[2 * 128 * 20];
    __shared__ float sB[2 * 16 * 136];
    int b   = blockIdx.z;
    int hw0 = blockIdx.x * 128;
    int k0  = blockIdx.y * 128;
    int tid = threadIdx.x;
    int lane = tid & 31, w = tid >> 5, wm = w >> 2, wn = w & 3;

    float acc[4][4][4];
    #pragma unroll
    for (int i = 0; i < 4; i++)
        #pragma unroll
        for (int j = 0; j < 4; j++)
            #pragma unroll
            for (int c = 0; c < 4; c++) acc[i][j][c] = 0.0f;

    const float* Ab = g_tn + (size_t)(b * K + k0) * D;
    const float* Bb = x + (size_t)b * D * HW + hw0;

    stage_rows20(Ab, D, 0, sA, tid);
    stage_bdots(Bb, 0, sB, tid);
    CP_COMMIT();
    const int NC = D / 16;   // 16
    for (int c = 0; c < NC; c++) {
        float* cA = sA + (c & 1) * (128 * 20);
        float* cB = sB + (c & 1) * (16 * 136);
        if (c + 1 < NC) {
            stage_rows20(Ab, D, (c + 1) * 16, sA + ((c + 1) & 1) * (128 * 20), tid);
            stage_bdots(Bb, (c + 1) * 16, sB + ((c + 1) & 1) * (16 * 136), tid);
            CP_COMMIT();
            CP_WAIT_1();
        } else {
            CP_WAIT_0();
        }
        __syncthreads();
        mma_compute_dots(cA, cB, acc, lane, wm, wn);
        __syncthreads();
    }

    int g = lane >> 2, t2 = (lane & 3) * 2;
    #pragma unroll
    for (int j = 0; j < 4; j++) {
        int col = hw0 + wn * 32 + j * 8 + t2;
        float2 inx = *(const float2*)(g_invnx + b * HW + col);
        #pragma unroll
        for (int i = 0; i < 4; i++) {
            int r0 = k0 + wm * 64 + i * 16 + g;
            float* o0 = g_p + (size_t)(b * K + r0) * HW + col;
            float* o1 = g_p + (size_t)(b * K + r0 + 8) * HW + col;
            *(float2*)o0 = make_float2(acc[i][j][0] * inx.x, acc[i][j][1] * inx.y);
            *(float2*)o1 = make_float2(acc[i][j][2] * inx.x, acc[i][j][3] * inx.y);
        }
    }
}

// ---------------- softmax over K per (b,hw) ----------------
__global__ void k_softmax() {
    int idx = blockIdx.x * 256 + threadIdx.x;
    int b = idx >> 12, hw = idx & (HW - 1);
    float* p = g_p + (size_t)b * K * HW + hw;
    float s = 0.0f;
    for (int k = 0; k < K; k++) {
        float e = __expf(p[(size_t)k * HW] * TEMP_INV);
        s += e;
        p[(size_t)k * HW] = e;
    }
    float rs = 1.0f / s;
    for (int k = 0; k < K; k++) p[(size_t)k * HW] *= rs;
}

__global__ void k_S() {
    __shared__ float sm[8];
    int bk = blockIdx.x;
    const float* p = g_p + (size_t)bk * HW;
    float s = 0.0f;
    for (int i = threadIdx.x; i < HW; i += 256) s += p[i];
    s = block_reduce_sum_256(s, sm);
    if (threadIdx.x == 0) g_S[bk] = s;
}

// ---------------- tgt2: y = tgt + (P x^T + EPS*xsum)/S_tot ----------------
__global__ void __launch_bounds__(256) k_tgt2(const float* __restrict__ x,
                                              const float* __restrict__ tgt) {
    __shared__ float sA[2 * 128 * 20];
    __shared__ float sB[2 * 128 * 20];
    int b  = blockIdx.z;
    int k0 = blockIdx.y * 128;
    int d0 = blockIdx.x * 128;

    float acc[4][4][4];
    #pragma unroll
    for (int i = 0; i < 4; i++)
        #pragma unroll
        for (int j = 0; j < 4; j++)
            #pragma unroll
            for (int c = 0; c < 4; c++) acc[i][j][c] = 0.0f;

    run_gemm_tn(g_p + (size_t)(b * K + k0) * HW, HW,
                x + (size_t)(b * D + d0) * HW, HW, HW, acc, sA, sB);

    int lane = threadIdx.x & 31, w = threadIdx.x >> 5, wm = w >> 2, wn = w & 3;
    int g = lane >> 2, t2 = (lane & 3) * 2;
    #pragma unroll
    for (int j = 0; j < 4; j++) {
        int col = d0 + wn * 32 + j * 8 + t2;
        float2 xsv = *(const float2*)(g_xsum + b * D + col);
        float xs0 = xsv.x * EPS_F, xs1 = xsv.y * EPS_F;
        #pragma unroll
        for (int i = 0; i < 4; i++) {
            int r0 = k0 + wm * 64 + i * 16 + g;
            float rs0 = 1.0f / (g_S[b * K + r0] + EPS_F * (float)HW);
            float rs1 = 1.0f / (g_S[b * K + r0 + 8] + EPS_F * (float)HW);
            size_t base0 = (size_t)(b * K + r0) * D + col;
            size_t base1 = (size_t)(b * K + r0 + 8) * D + col;
            float2 t0 = *(const float2*)(tgt + base0);
            float2 t1 = *(const float2*)(tgt + base1);
            *(float2*)(g_y + base0) = make_float2((acc[i][j][0] + xs0) * rs0 + t0.x,
                                                  (acc[i][j][1] + xs1) * rs0 + t0.y);
            *(float2*)(g_y + base1) = make_float2((acc[i][j][2] + xs0) * rs1 + t1.x,
                                                  (acc[i][j][3] + xs1) * rs1 + t1.y);
        }
    }
}

// ---------------- LayerNorms ----------------
__global__ void k_ln1(const float* __restrict__ gamma,
                      const float* __restrict__ beta) {
    __shared__ float sm[8];
    int row = blockIdx.x;
    float v  = g_y[row * D + threadIdx.x];
    float mu = block_reduce_sum_256(v, sm) * (1.0f / D);
    float d  = v - mu;
    float var = block_reduce_sum_256(d * d, sm) * (1.0f / D);
    float r = rsqrtf(var + LN_EPS);
    g_t[row * D + threadIdx.x] = d * r * gamma[threadIdx.x] + beta[threadIdx.x];
}

__global__ void k_ln2(const float* __restrict__ gamma,
                      const float* __restrict__ beta,
                      float* __restrict__ dst) {
    __shared__ float sm[8];
    int row = blockIdx.x;
    float v  = g_y[row * D + threadIdx.x];
    float mu = block_reduce_sum_256(v, sm) * (1.0f / D);
    float d  = v - mu;
    float var = block_reduce_sum_256(d * d, sm) * (1.0f / D);
    float r = rsqrtf(var + LN_EPS);
    dst[row * D + threadIdx.x] = d * r * gamma[threadIdx.x] + beta[threadIdx.x];
}

// ---------------- FFN1: h = relu(t @ w1^T + b1) ----------------
__global__ void __launch_bounds__(256) k_ffn1(const float* __restrict__ w1,
                                              const float* __restrict__ b1) {
    __shared__ float sA[2 * 128 * 20];
    __shared__ float sB[2 * 128 * 20];
    int m0 = blockIdx.y * 128;
    int f0 = blockIdx.x * 128;

    float acc[4][4][4];
    #pragma unroll
    for (int i = 0; i < 4; i++)
        #pragma unroll
        for (int j = 0; j < 4; j++)
            #pragma unroll
            for (int c = 0; c < 4; c++) acc[i][j][c] = 0.0f;

    run_gemm_tn(g_t + (size_t)m0 * D, D, w1 + (size_t)f0 * D, D, D, acc, sA, sB);

    int lane = threadIdx.x & 31, w = threadIdx.x >> 5, wm = w >> 2, wn = w & 3;
    int g = lane >> 2, t2 = (lane & 3) * 2;
    #pragma unroll
    for (int j = 0; j < 4; j++) {
        int col = f0 + wn * 32 + j * 8 + t2;
        float2 bias = *(const float2*)(b1 + col);
        #pragma unroll
        for (int i = 0; i < 4; i++) {
            int r0 = m0 + wm * 64 + i * 16 + g;
            *(float2*)(g_h + (size_t)r0 * DFF + col) =
                make_float2(fmaxf(acc[i][j][0] + bias.x, 0.0f),
                            fmaxf(acc[i][j][1] + bias.y, 0.0f));
            *(float2*)(g_h + (size_t)(r0 + 8) * DFF + col) =
                make_float2(fmaxf(acc[i][j][2] + bias.x, 0.0f),
                            fmaxf(acc[i][j][3] + bias.y, 0.0f));
        }
    }
}

// ---------------- FFN2 + residual: y = t + h @ w2^T + b2 ----------------
__global__ void __launch_bounds__(256) k_ffn2(const float* __restrict__ w2,
                                              const float* __restrict__ b2) {
    __shared__ float sA[2 * 128 * 20];
    __shared__ float sB[2 * 128 * 20];
    int m0 = blockIdx.y * 128;
    int d0 = blockIdx.x * 128;

    float acc[4][4][4];
    #pragma unroll
    for (int i = 0; i < 4; i++)
        #pragma unroll
        for (int j = 0; j < 4; j++)
            #pragma unroll
            for (int c = 0; c < 4; c++) acc[i][j][c] = 0.0f;

    run_gemm_tn(g_h + (size_t)m0 * DFF, DFF, w2 + (size_t)d0 * DFF, DFF, DFF, acc, sA, sB);

    int lane = threadIdx.x & 31, w = threadIdx.x >> 5, wm = w >> 2, wn = w & 3;
    int g = lane >> 2, t2 = (lane & 3) * 2;
    #pragma unroll
    for (int j = 0; j < 4; j++) {
        int col = d0 + wn * 32 + j * 8 + t2;
        float2 bias = *(const float2*)(b2 + col);
        #pragma unroll
        for (int i = 0; i < 4; i++) {
            int r0 = m0 + wm * 64 + i * 16 + g;
            size_t base0 = (size_t)r0 * D + col;
            size_t base1 = (size_t)(r0 + 8) * D + col;
            float2 t0 = *(const float2*)(g_t + base0);
            float2 t1 = *(const float2*)(g_t + base1);
            *(float2*)(g_y + base0) = make_float2(acc[i][j][0] + bias.x + t0.x,
                                                  acc[i][j][1] + bias.y + t0.y);
            *(float2*)(g_y + base1) = make_float2(acc[i][j][2] + bias.x + t1.x,
                                                  acc[i][j][3] + bias.y + t1.y);
        }
    }
}

// ---------------- launch ----------------
extern "C" void kernel_launch(void* const* d_in, const int* in_sizes, int n_in,
                              void* d_out, int out_size) {
    const float* x   = (const float*)d_in[0];
    const float* tgt = (const float*)d_in[1];
    const float* w1  = (const float*)d_in[2];
    const float* b1  = (const float*)d_in[3];
    const float* w2  = (const float*)d_in[4];
    const float* b2  = (const float*)d_in[5];
    const float* g2  = (const float*)d_in[6];
    const float* be2 = (const float*)d_in[7];
    const float* g3  = (const float*)d_in[8];
    const float* be3 = (const float*)d_in[9];
    float* out = (float*)d_out;

    k_tn   <<<B * K, 256>>>(tgt);
    k_invnx<<<(B * HW) / 256, 256>>>(x);
    k_xsum <<<B * D, 256>>>(x);

    k_dots <<<dim3(HW / 128, K / 128, B), 256>>>(x);
    k_softmax<<<(B * HW) / 256, 256>>>();
    k_S    <<<B * K, 256>>>();

    k_tgt2 <<<dim3(D / 128, K / 128, B), 256>>>(x, tgt);
    k_ln1  <<<B * K, 256>>>(g2, be2);

    k_ffn1 <<<dim3(DFF / 128, (B * K) / 128), 256>>>(w1, b1);
    k_ffn2 <<<dim3(D / 128, (B * K) / 128), 256>>>(w2, b2);
    k_ln2  <<<B * K, 256>>>(g3, be3, out);
}